// round 17
// baseline (speedup 1.0000x reference)
#include <cuda_runtime.h>
#include <cuda_bf16.h>
#include <cuda_fp16.h>
#include <cstdint>
#include <math.h>

#define N_NODES 100000
#define NFEAT   512
#define NHID    256
#define NCLASS  40
#define NEDGE   1600000
#define KHOPS   10
#define ALPHA_F 0.1f
#define NBLK    391   // ceil(100000/256)

// ---------------- scratch (device globals; no allocs allowed) ----------------
__device__ __half         g_h2h[(size_t)N_NODES * NCLASS]; // 8 MB (fp16 h2)
__device__ __half         g_zha[(size_t)N_NODES * NCLASS]; // 8 MB (fp16 z ping)
__device__ __half         g_zhb[(size_t)N_NODES * NCLASS]; // 8 MB (fp16 z pong)
__device__ __nv_bfloat16  g_xb [(size_t)N_NODES * NFEAT];  // 102.4 MB (bf16 x)
__device__ __nv_bfloat16  g_w1b[(size_t)NHID * NFEAT];     // 256 KB (W1^T bf16 [N][K])
__device__ __nv_bfloat16  g_w2t[(size_t)NCLASS * NHID];    // 20 KB (W2^T bf16 [N][K])
__device__ int   g_deg[N_NODES];
__device__ int   g_rowptr[N_NODES + 1];
__device__ int   g_cursor[N_NODES];
__device__ int   g_bpart[512];
__device__ int   g_boff[512];
__device__ int2  g_cedge[NEDGE];                           // 12.8 MB {src, val bits}

// ---------------- PTX helpers ----------------
__device__ __forceinline__ void cp_async16(uint32_t saddr, const void* gaddr) {
    asm volatile("cp.async.cg.shared.global [%0], [%1], 16;\n" :: "r"(saddr), "l"(gaddr));
}
__device__ __forceinline__ void cp_commit() {
    asm volatile("cp.async.commit_group;\n" ::: "memory");
}
__device__ __forceinline__ void cp_wait1() {
    asm volatile("cp.async.wait_group 1;\n" ::: "memory");
}
__device__ __forceinline__ void ldsm_x4(uint32_t& r0, uint32_t& r1, uint32_t& r2,
                                        uint32_t& r3, uint32_t addr) {
    asm volatile("ldmatrix.sync.aligned.m8n8.x4.shared.b16 {%0,%1,%2,%3}, [%4];"
                 : "=r"(r0), "=r"(r1), "=r"(r2), "=r"(r3) : "r"(addr));
}

// ---------------- bf16 conversions ----------------
__global__ void __launch_bounds__(256)
conv_x_kernel(const float* __restrict__ x, __nv_bfloat16* __restrict__ xb)
{
    int i = blockIdx.x * 256 + threadIdx.x;         // per 8 floats
    const int n8 = N_NODES * NFEAT / 8;
    if (i < n8) {
        float4 a = ((const float4*)x)[2 * i];
        float4 b = ((const float4*)x)[2 * i + 1];
        __nv_bfloat162 p0 = __floats2bfloat162_rn(a.x, a.y);
        __nv_bfloat162 p1 = __floats2bfloat162_rn(a.z, a.w);
        __nv_bfloat162 p2 = __floats2bfloat162_rn(b.x, b.y);
        __nv_bfloat162 p3 = __floats2bfloat162_rn(b.z, b.w);
        uint4 o;
        o.x = *reinterpret_cast<unsigned*>(&p0);
        o.y = *reinterpret_cast<unsigned*>(&p1);
        o.z = *reinterpret_cast<unsigned*>(&p2);
        o.w = *reinterpret_cast<unsigned*>(&p3);
        ((uint4*)xb)[i] = o;
    }
}

__global__ void __launch_bounds__(256)
conv_w1_kernel(const float* __restrict__ W1, __nv_bfloat16* __restrict__ w1b)
{
    int id = blockIdx.x * 256 + threadIdx.x;        // (n,k), k fast
    if (id < NHID * NFEAT) {
        int n = id >> 9;
        int k = id & 511;
        w1b[id] = __float2bfloat16(W1[(size_t)k * NHID + n]);
    }
}

__global__ void __launch_bounds__(256)
conv_w2_kernel(const float* __restrict__ W2, __nv_bfloat16* __restrict__ w2t)
{
    int id = blockIdx.x * 256 + threadIdx.x;        // (n,k), k fast
    if (id < NCLASS * NHID) {
        int n = id >> 8;
        int k = id & 255;
        w2t[id] = __float2bfloat16(W2[(size_t)k * NCLASS + n]);
    }
}

// ====== fused GEMM1+GEMM2 v2: CTA = 128 rows x FULL 256 hidden cols ==========
// 512 threads, 16 warps (warp tile 64x32). Mainloop: bf16 mma + ldmatrix,
// double-buffered cp.async (A 128xK, B 256xK). Epilogue: stage relu(h)+b1 to
// smem (full 128x256 tile), then warps 0..7 run gemm2 K=256 and write fp16
// h2h (+b2) directly. No split-K, no atomics, x read ONCE.
#define G1_BK   32
#define G1_STR  40
#define SM_ABUF 10240u                   // per-buffer A: 128*40*2
#define SM_BOFF 20480u                   // Bs base
#define SM_BBUF 20480u                   // per-buffer B: 256*40*2
#define HS_STR  264
#define SM_W2S  67584u                   // Hs = 128*264*2
#define SM_TOT  88704u                   // + W2s = 40*264*2

__global__ void __launch_bounds__(512, 1)
gemm_fused_kernel(const __nv_bfloat16* __restrict__ xb,
                  const __nv_bfloat16* __restrict__ w1b,
                  const __nv_bfloat16* __restrict__ w2t,
                  const float* __restrict__ b1, const float* __restrict__ b2,
                  __half* __restrict__ h2h)
{
    extern __shared__ __align__(16) char sm[];

    const int tid  = threadIdx.x;
    const int warp = tid >> 5;     // 0..15
    const int lane = tid & 31;
    const int grp  = lane >> 2;
    const int tig  = lane & 3;
    const int warp_m = warp & 1;   // 0..1
    const int warp_n = warp >> 1;  // 0..7

    const int m0 = blockIdx.x * 128;

    const uint32_t sbase = (uint32_t)__cvta_generic_to_shared(sm);

    const int lm_row = lane & 15;
    const int lm_kof = (lane >> 4) * 8;

    float acc[4][4][4];
    #pragma unroll
    for (int i = 0; i < 4; i++)
        #pragma unroll
        for (int j = 0; j < 4; j++)
            #pragma unroll
            for (int r = 0; r < 4; r++) acc[i][j][r] = 0.f;

    // loaders: A = 512 x 16B chunks (1/thread); B = 1024 chunks (2/thread)
    const int ar = tid >> 2, ak = (tid & 3) * 8;
    const int gr = min(m0 + ar, N_NODES - 1);
    const int bc0 = tid, bc1 = tid + 512;
    const int br0 = bc0 >> 2, bk0 = (bc0 & 3) * 8;
    const int br1 = bc1 >> 2, bk1 = (bc1 & 3) * 8;

    const int NT = NFEAT / G1_BK;  // 16

    auto load_tile = [&](int kt, int b) {
        const int kb = kt * G1_BK;
        const uint32_t ab = sbase + (uint32_t)b * SM_ABUF;
        const uint32_t bb = sbase + SM_BOFF + (uint32_t)b * SM_BBUF;
        cp_async16(ab + (uint32_t)((ar * G1_STR + ak) * 2),
                   xb + (size_t)gr * NFEAT + kb + ak);
        cp_async16(bb + (uint32_t)((br0 * G1_STR + bk0) * 2),
                   w1b + (size_t)br0 * NFEAT + kb + bk0);
        cp_async16(bb + (uint32_t)((br1 * G1_STR + bk1) * 2),
                   w1b + (size_t)br1 * NFEAT + kb + bk1);
    };

    load_tile(0, 0);
    cp_commit();

    for (int kt = 0; kt < NT; kt++) {
        if (kt + 1 < NT) load_tile(kt + 1, (kt + 1) & 1);
        cp_commit();
        cp_wait1();
        __syncthreads();

        const int buf = kt & 1;
        const uint32_t abuf = sbase + (uint32_t)buf * SM_ABUF;
        const uint32_t bbuf = sbase + SM_BOFF + (uint32_t)buf * SM_BBUF;
        #pragma unroll
        for (int ks = 0; ks < 2; ks++) {
            const int kb = ks * 16 + lm_kof;
            uint32_t a[4][4], b[4][2];
            #pragma unroll
            for (int mf = 0; mf < 4; mf++) {
                const int r = warp_m * 64 + mf * 16 + lm_row;
                ldsm_x4(a[mf][0], a[mf][1], a[mf][2], a[mf][3],
                        abuf + (uint32_t)((r * G1_STR + kb) * 2));
            }
            #pragma unroll
            for (int np = 0; np < 2; np++) {
                const int cn = warp_n * 32 + np * 16 + lm_row;
                ldsm_x4(b[2*np][0], b[2*np + 1][0], b[2*np][1], b[2*np + 1][1],
                        bbuf + (uint32_t)((cn * G1_STR + kb) * 2));
            }
            #pragma unroll
            for (int mf = 0; mf < 4; mf++)
                #pragma unroll
                for (int nf = 0; nf < 4; nf++) {
                    asm volatile(
                        "mma.sync.aligned.m16n8k16.row.col.f32.bf16.bf16.f32 "
                        "{%0,%1,%2,%3}, {%4,%5,%6,%7}, {%8,%9}, {%0,%1,%2,%3};\n"
                        : "+f"(acc[mf][nf][0]), "+f"(acc[mf][nf][1]),
                          "+f"(acc[mf][nf][2]), "+f"(acc[mf][nf][3])
                        : "r"(a[mf][0]), "r"(a[mf][1]), "r"(a[mf][2]), "r"(a[mf][3]),
                          "r"(b[nf][0]), "r"(b[nf][1]));
                }
        }
        __syncthreads();
    }

    // ---- phase B: stage relu(h)+b1 full tile (128x256) -> Hs; load W2^T -----
    __nv_bfloat16* Hs  = (__nv_bfloat16*)sm;                 // [128][264]
    __nv_bfloat16* W2s = (__nv_bfloat16*)(sm + SM_W2S);      // [40][264]

    #pragma unroll
    for (int nf = 0; nf < 4; nf++) {
        const int cl = warp_n * 32 + nf * 8 + 2 * tig;       // hidden col 0..255
        const float bx = b1[cl], by = b1[cl + 1];
        #pragma unroll
        for (int mf = 0; mf < 4; mf++) {
            const int rl = warp_m * 64 + mf * 16 + grp;       // local row
            __nv_bfloat162 o0 = __floats2bfloat162_rn(
                fmaxf(acc[mf][nf][0] + bx, 0.f),
                fmaxf(acc[mf][nf][1] + by, 0.f));
            *(uint32_t*)&Hs[rl * HS_STR + cl] = *reinterpret_cast<uint32_t*>(&o0);
            __nv_bfloat162 o1 = __floats2bfloat162_rn(
                fmaxf(acc[mf][nf][2] + bx, 0.f),
                fmaxf(acc[mf][nf][3] + by, 0.f));
            *(uint32_t*)&Hs[(rl + 8) * HS_STR + cl] = *reinterpret_cast<uint32_t*>(&o1);
        }
    }
    // W2s[c][k] = w2t[c][k]; 40*256 bf16 = 1280 x 8-elem chunks
    for (int t = tid; t < 1280; t += 512) {
        int c = t >> 5;
        int k = (t & 31) * 8;
        *(uint4*)&W2s[c * HS_STR + k] = *(const uint4*)&w2t[(size_t)c * NHID + k];
    }
    __syncthreads();

    // ---- gemm2 (full K=256): warps 0..7, warp w -> rows m0+w*16+{grp,grp+8} -
    if (warp < 8) {
        float a2[5][4];
        #pragma unroll
        for (int j = 0; j < 5; j++)
            #pragma unroll
            for (int r = 0; r < 4; r++) a2[j][r] = 0.f;

        #pragma unroll
        for (int kt2 = 0; kt2 < 16; kt2++) {
            const int kb = kt2 * 16;
            uint32_t a[4], b[5][2];
            const int r = warp * 16 + grp;
            a[0] = *(const uint32_t*)&Hs[ r      * HS_STR + kb + tig * 2    ];
            a[1] = *(const uint32_t*)&Hs[(r + 8) * HS_STR + kb + tig * 2    ];
            a[2] = *(const uint32_t*)&Hs[ r      * HS_STR + kb + tig * 2 + 8];
            a[3] = *(const uint32_t*)&Hs[(r + 8) * HS_STR + kb + tig * 2 + 8];
            #pragma unroll
            for (int nf = 0; nf < 5; nf++) {
                const int cn = nf * 8 + grp;
                b[nf][0] = *(const uint32_t*)&W2s[cn * HS_STR + kb + tig * 2    ];
                b[nf][1] = *(const uint32_t*)&W2s[cn * HS_STR + kb + tig * 2 + 8];
            }
            #pragma unroll
            for (int nf = 0; nf < 5; nf++) {
                asm volatile(
                    "mma.sync.aligned.m16n8k16.row.col.f32.bf16.bf16.f32 "
                    "{%0,%1,%2,%3}, {%4,%5,%6,%7}, {%8,%9}, {%0,%1,%2,%3};\n"
                    : "+f"(a2[nf][0]), "+f"(a2[nf][1]),
                      "+f"(a2[nf][2]), "+f"(a2[nf][3])
                    : "r"(a[0]), "r"(a[1]), "r"(a[2]), "r"(a[3]),
                      "r"(b[nf][0]), "r"(b[nf][1]));
            }
        }

        const int rg = m0 + warp * 16 + grp;
        #pragma unroll
        for (int nf = 0; nf < 5; nf++) {
            const int col = nf * 8 + 2 * tig;
            const float bx = b2[col], by = b2[col + 1];
            if (rg < N_NODES) {
                __half2 o = __floats2half2_rn(a2[nf][0] + bx, a2[nf][1] + by);
                *(uint32_t*)&h2h[(size_t)rg * NCLASS + col] =
                    *reinterpret_cast<uint32_t*>(&o);
            }
            if (rg + 8 < N_NODES) {
                __half2 o = __floats2half2_rn(a2[nf][2] + bx, a2[nf][3] + by);
                *(uint32_t*)&h2h[(size_t)(rg + 8) * NCLASS + col] =
                    *reinterpret_cast<uint32_t*>(&o);
            }
        }
    }
}

// ================= CSR build (by dst), full-chip 3-phase scan ================
__global__ void __launch_bounds__(256)
zero_deg_kernel(int* __restrict__ deg)
{
    int i = blockIdx.x * 256 + threadIdx.x;
    if (i < N_NODES) deg[i] = 0;
}

__global__ void __launch_bounds__(256)
hist_kernel(const int* __restrict__ edst, int* __restrict__ deg)
{
    int e = blockIdx.x * 256 + threadIdx.x;
    if (e < NEDGE) atomicAdd(&deg[edst[e]], 1);
}

__global__ void __launch_bounds__(256)
partial_kernel(const int* __restrict__ deg, int* __restrict__ bpart)
{
    __shared__ int red[256];
    const int tid = threadIdx.x;
    const int i = blockIdx.x * 256 + tid;
    red[tid] = (i < N_NODES) ? deg[i] : 0;
    __syncthreads();
    #pragma unroll
    for (int off = 128; off > 0; off >>= 1) {
        if (tid < off) red[tid] += red[tid + off];
        __syncthreads();
    }
    if (tid == 0) bpart[blockIdx.x] = red[0];
}

__global__ void __launch_bounds__(512)
scanpart_kernel(const int* __restrict__ bpart, int* __restrict__ boff)
{
    __shared__ int s[512];
    const int tid = threadIdx.x;
    int v = (tid < NBLK) ? bpart[tid] : 0;
    s[tid] = v;
    __syncthreads();
    for (int off = 1; off < 512; off <<= 1) {
        int t = (tid >= off) ? s[tid - off] : 0;
        __syncthreads();
        s[tid] += t;
        __syncthreads();
    }
    if (tid < NBLK) boff[tid] = s[tid] - v;   // exclusive
}

__global__ void __launch_bounds__(256)
rowptr_kernel(const int* __restrict__ deg, const int* __restrict__ boff,
              int* __restrict__ rowptr, int* __restrict__ cursor)
{
    __shared__ int s[256];
    const int tid = threadIdx.x;
    const int i = blockIdx.x * 256 + tid;
    int v = (i < N_NODES) ? deg[i] : 0;
    s[tid] = v;
    __syncthreads();
    for (int off = 1; off < 256; off <<= 1) {
        int t = (tid >= off) ? s[tid - off] : 0;
        __syncthreads();
        s[tid] += t;
        __syncthreads();
    }
    const int base = boff[blockIdx.x];
    if (i < N_NODES) {
        int excl = base + s[tid] - v;
        rowptr[i] = excl;
        cursor[i] = excl;
        if (i == N_NODES - 1) rowptr[N_NODES] = excl + v;
    }
}

__global__ void __launch_bounds__(256)
scatter_kernel(const int* __restrict__ esrc, const int* __restrict__ edst,
               const float* __restrict__ eval_, int* __restrict__ cursor,
               int2* __restrict__ cedge)
{
    int e = blockIdx.x * 256 + threadIdx.x;
    if (e < NEDGE) {
        int d = edst[e];
        int slot = atomicAdd(&cursor[d], 1);
        cedge[slot] = make_int2(esrc[e],
                                __float_as_int((1.0f - ALPHA_F) * eval_[e]));
    }
}

// ======== propagation hop: zout[dst] = alpha*h2h[dst] + sum ev*zin[src] ======
template<int OUT16>
__global__ void __launch_bounds__(256)
prop_kernel(const int* __restrict__ rowptr, const int2* __restrict__ cedge,
            const __half* __restrict__ h2h,
            const __half* __restrict__ zin, void* __restrict__ zout_)
{
    int idx = blockIdx.x * 256 + threadIdx.x;
    if (idx >= N_NODES * 10) return;
    int dst = idx / 10;
    int g = idx - dst * 10;
    const int col = g * 4;

    int e  = rowptr[dst];
    int e1 = rowptr[dst + 1];

    auto loadz = [&](int src) -> float4 {
        const __half* z = zin + (size_t)src * NCLASS + col;
        uint2 r = __ldg((const uint2*)z);
        __half2 p0 = *reinterpret_cast<__half2*>(&r.x);
        __half2 p1 = *reinterpret_cast<__half2*>(&r.y);
        float2 f0 = __half22float2(p0);
        float2 f1 = __half22float2(p1);
        return make_float4(f0.x, f0.y, f1.x, f1.y);
    };

    float4 acc0, acc1;
    {
        uint2 r = __ldg((const uint2*)(h2h + (size_t)dst * NCLASS + col));
        __half2 p0 = *reinterpret_cast<__half2*>(&r.x);
        __half2 p1 = *reinterpret_cast<__half2*>(&r.y);
        float2 f0 = __half22float2(p0);
        float2 f1 = __half22float2(p1);
        acc0 = make_float4(ALPHA_F * f0.x, ALPHA_F * f0.y,
                           ALPHA_F * f1.x, ALPHA_F * f1.y);
        acc1 = make_float4(0.f, 0.f, 0.f, 0.f);
    }

    for (; e + 8 <= e1; e += 8) {
        int2 d0 = cedge[e    ], d1 = cedge[e + 1], d2 = cedge[e + 2], d3 = cedge[e + 3];
        int2 d4 = cedge[e + 4], d5 = cedge[e + 5], d6 = cedge[e + 6], d7 = cedge[e + 7];
        float4 z0 = loadz(d0.x), z1 = loadz(d1.x), z2 = loadz(d2.x), z3 = loadz(d3.x);
        float4 z4 = loadz(d4.x), z5 = loadz(d5.x), z6 = loadz(d6.x), z7 = loadz(d7.x);
        float v0 = __int_as_float(d0.y), v1 = __int_as_float(d1.y);
        float v2 = __int_as_float(d2.y), v3 = __int_as_float(d3.y);
        float v4 = __int_as_float(d4.y), v5 = __int_as_float(d5.y);
        float v6 = __int_as_float(d6.y), v7 = __int_as_float(d7.y);
        acc0.x = fmaf(v0, z0.x, acc0.x); acc0.y = fmaf(v0, z0.y, acc0.y);
        acc0.z = fmaf(v0, z0.z, acc0.z); acc0.w = fmaf(v0, z0.w, acc0.w);
        acc1.x = fmaf(v1, z1.x, acc1.x); acc1.y = fmaf(v1, z1.y, acc1.y);
        acc1.z = fmaf(v1, z1.z, acc1.z); acc1.w = fmaf(v1, z1.w, acc1.w);
        acc0.x = fmaf(v2, z2.x, acc0.x); acc0.y = fmaf(v2, z2.y, acc0.y);
        acc0.z = fmaf(v2, z2.z, acc0.z); acc0.w = fmaf(v2, z2.w, acc0.w);
        acc1.x = fmaf(v3, z3.x, acc1.x); acc1.y = fmaf(v3, z3.y, acc1.y);
        acc1.z = fmaf(v3, z3.z, acc1.z); acc1.w = fmaf(v3, z3.w, acc1.w);
        acc0.x = fmaf(v4, z4.x, acc0.x); acc0.y = fmaf(v4, z4.y, acc0.y);
        acc0.z = fmaf(v4, z4.z, acc0.z); acc0.w = fmaf(v4, z4.w, acc0.w);
        acc1.x = fmaf(v5, z5.x, acc1.x); acc1.y = fmaf(v5, z5.y, acc1.y);
        acc1.z = fmaf(v5, z5.z, acc1.z); acc1.w = fmaf(v5, z5.w, acc1.w);
        acc0.x = fmaf(v6, z6.x, acc0.x); acc0.y = fmaf(v6, z6.y, acc0.y);
        acc0.z = fmaf(v6, z6.z, acc0.z); acc0.w = fmaf(v6, z6.w, acc0.w);
        acc1.x = fmaf(v7, z7.x, acc1.x); acc1.y = fmaf(v7, z7.y, acc1.y);
        acc1.z = fmaf(v7, z7.z, acc1.z); acc1.w = fmaf(v7, z7.w, acc1.w);
    }
    for (; e + 2 <= e1; e += 2) {
        int2 d0 = cedge[e], d1 = cedge[e + 1];
        float4 z0 = loadz(d0.x), z1 = loadz(d1.x);
        float v0 = __int_as_float(d0.y), v1 = __int_as_float(d1.y);
        acc0.x = fmaf(v0, z0.x, acc0.x); acc0.y = fmaf(v0, z0.y, acc0.y);
        acc0.z = fmaf(v0, z0.z, acc0.z); acc0.w = fmaf(v0, z0.w, acc0.w);
        acc1.x = fmaf(v1, z1.x, acc1.x); acc1.y = fmaf(v1, z1.y, acc1.y);
        acc1.z = fmaf(v1, z1.z, acc1.z); acc1.w = fmaf(v1, z1.w, acc1.w);
    }
    if (e < e1) {
        int2 d0 = cedge[e];
        float4 z0 = loadz(d0.x);
        float v0 = __int_as_float(d0.y);
        acc0.x = fmaf(v0, z0.x, acc0.x); acc0.y = fmaf(v0, z0.y, acc0.y);
        acc0.z = fmaf(v0, z0.z, acc0.z); acc0.w = fmaf(v0, z0.w, acc0.w);
    }
    acc0.x += acc1.x; acc0.y += acc1.y; acc0.z += acc1.z; acc0.w += acc1.w;

    if (OUT16) {
        __half2 p0 = __floats2half2_rn(acc0.x, acc0.y);
        __half2 p1 = __floats2half2_rn(acc0.z, acc0.w);
        uint2 o;
        o.x = *reinterpret_cast<uint32_t*>(&p0);
        o.y = *reinterpret_cast<uint32_t*>(&p1);
        *(uint2*)((__half*)zout_ + (size_t)dst * NCLASS + col) = o;
    } else {
        *(float4*)((float*)zout_ + (size_t)dst * NCLASS + col) = acc0;
    }
}

// ---------------- log_softmax per row ----------------
__global__ void __launch_bounds__(256)
softmax_kernel(const float* __restrict__ z, float* __restrict__ out)
{
    int row = blockIdx.x * 8 + (threadIdx.x >> 5);
    int lane = threadIdx.x & 31;
    if (row >= N_NODES) return;
    const float* zr = z + (size_t)row * NCLASS;
    float v0 = zr[lane];
    bool has2 = (lane + 32) < NCLASS;
    float v1 = has2 ? zr[lane + 32] : -3.402823466e38f;
    float m = fmaxf(v0, v1);
    #pragma unroll
    for (int o = 16; o > 0; o >>= 1) m = fmaxf(m, __shfl_xor_sync(0xffffffffu, m, o));
    float s = __expf(v0 - m) + (has2 ? __expf(v1 - m) : 0.f);
    #pragma unroll
    for (int o = 16; o > 0; o >>= 1) s += __shfl_xor_sync(0xffffffffu, s, o);
    float lse = m + __logf(s);
    float* orow = out + (size_t)row * NCLASS;
    orow[lane] = v0 - lse;
    if (has2) orow[lane + 32] = v1 - lse;
}

// ---------------- launch ----------------
extern "C" void kernel_launch(void* const* d_in, const int* in_sizes, int n_in,
                              void* d_out, int out_size)
{
    const float* x     = (const float*)d_in[0];
    const int*   esrc  = (const int*)  d_in[1];
    const int*   edst  = (const int*)  d_in[2];
    const float* eval_ = (const float*)d_in[3];
    const float* W1    = (const float*)d_in[4];
    const float* b1    = (const float*)d_in[5];
    const float* W2    = (const float*)d_in[6];
    const float* b2    = (const float*)d_in[7];
    float* out = (float*)d_out;

    __half *h2h, *zha, *zhb;
    __nv_bfloat16 *xb, *w1b, *w2t;
    int *deg, *rowptr, *cursor, *bpart, *boff;
    int2 *cedge;
    cudaGetSymbolAddress((void**)&h2h,    g_h2h);
    cudaGetSymbolAddress((void**)&zha,    g_zha);
    cudaGetSymbolAddress((void**)&zhb,    g_zhb);
    cudaGetSymbolAddress((void**)&xb,     g_xb);
    cudaGetSymbolAddress((void**)&w1b,    g_w1b);
    cudaGetSymbolAddress((void**)&w2t,    g_w2t);
    cudaGetSymbolAddress((void**)&deg,    g_deg);
    cudaGetSymbolAddress((void**)&rowptr, g_rowptr);
    cudaGetSymbolAddress((void**)&cursor, g_cursor);
    cudaGetSymbolAddress((void**)&bpart,  g_bpart);
    cudaGetSymbolAddress((void**)&boff,   g_boff);
    cudaGetSymbolAddress((void**)&cedge,  g_cedge);

    cudaFuncSetAttribute(gemm_fused_kernel,
                         cudaFuncAttributeMaxDynamicSharedMemorySize, SM_TOT);

    // conversions
    conv_x_kernel<<<(N_NODES * NFEAT / 8 + 255) / 256, 256>>>(x, xb);
    conv_w1_kernel<<<(NHID * NFEAT + 255) / 256, 256>>>(W1, w1b);
    conv_w2_kernel<<<(NCLASS * NHID + 255) / 256, 256>>>(W2, w2t);

    // fused GEMM1+GEMM2 -> h2h (fp16), single pass, no atomics
    gemm_fused_kernel<<<(N_NODES + 127) / 128, 512, SM_TOT>>>(
        xb, w1b, w2t, b1, b2, h2h);

    // CSR build (full-chip scan)
    zero_deg_kernel<<<NBLK, 256>>>(deg);
    hist_kernel<<<(NEDGE + 255) / 256, 256>>>(edst, deg);
    partial_kernel<<<NBLK, 256>>>(deg, bpart);
    scanpart_kernel<<<1, 512>>>(bpart, boff);
    rowptr_kernel<<<NBLK, 256>>>(deg, boff, rowptr, cursor);
    scatter_kernel<<<(NEDGE + 255) / 256, 256>>>(esrc, edst, eval_, cursor, cedge);

    const int prop_blocks = (N_NODES * 10 + 255) / 256;

    // hop 0: zin = h2h (fp16) -> zha
    prop_kernel<1><<<prop_blocks, 256>>>(rowptr, cedge, h2h, h2h, zha);
    // hops 1..8: fp16 ping-pong
    const __half* zi = zha;
    __half* zo = zhb;
    for (int i = 1; i < KHOPS - 1; i++) {
        prop_kernel<1><<<prop_blocks, 256>>>(rowptr, cedge, h2h, zi, zo);
        const __half* t = zo; zo = (__half*)zi; zi = t;
    }
    // hop 9: fp16 -> fp32 out
    prop_kernel<0><<<prop_blocks, 256>>>(rowptr, cedge, h2h, zi, out);

    softmax_kernel<<<(N_NODES + 7) / 8, 256>>>(out, out);
}